// round 1
// baseline (speedup 1.0000x reference)
#include <cuda_runtime.h>

// ---------------- problem constants ----------------
#define NN   100000      // nodes
#define NE   1600000     // edges
#define IND  256         // input dim
#define NH   4           // heads
#define DD   32          // hidden per head
#define CC   47          // classes
#define CPAD 48          // padded classes (float4-friendly)
#define F12  128         // H*D
#define F3   192         // H*CPAD
#define NEG  0.2f

// ---------------- scratch (no allocs allowed) ----------------
__device__ float g_feat[(size_t)NN * F3];   // GEMM output (feat) per layer
__device__ float g_agg [(size_t)NN * F3];   // aggregation output / next-layer input
__device__ float g_el  [NN * NH];
__device__ float g_er  [NN * NH];
__device__ float g_m   [NN * NH];
__device__ float g_den [NN * NH];
__device__ float g_W3p [F12 * F3];          // W3 padded 188 -> 192 cols

__device__ __forceinline__ float leaky(float x) { return x > 0.f ? x : NEG * x; }

__device__ __forceinline__ void atomicMaxF(float* addr, float v) {
    if (v >= 0.f) atomicMax((int*)addr, __float_as_int(v));
    else          atomicMin((unsigned int*)addr, __float_as_uint(v));
}

// ---------------- GEMM: g_feat = A[M,K] @ B[K,NC] ----------------
// 64x64 tile, 256 threads, 4x4 per-thread microtile, K-step 16.
__global__ void gemm64(const float* __restrict__ A, const float* __restrict__ B,
                       int M, int K, int NC)
{
    __shared__ float As[16][68];   // transposed A tile: As[k][m]
    __shared__ float Bs[16][68];   // Bs[k][n]
    int tid = threadIdx.x;
    int tx = tid & 15, ty = tid >> 4;
    int rowBase = blockIdx.y * 64;
    int colBase = blockIdx.x * 64;
    int lr = tid >> 2;            // 0..63  (A row in tile)
    int lk = (tid & 3) * 4;       // 0,4,8,12 (A k group)
    int bk = tid >> 4;            // 0..15  (B k)
    int bn = (tid & 15) * 4;      // B col group
    float acc[4][4] = {};

    for (int kt = 0; kt < K; kt += 16) {
        float4 av = make_float4(0.f, 0.f, 0.f, 0.f);
        int gr = rowBase + lr;
        if (gr < M) av = *(const float4*)(A + (size_t)gr * K + kt + lk);
        As[lk + 0][lr] = av.x; As[lk + 1][lr] = av.y;
        As[lk + 2][lr] = av.z; As[lk + 3][lr] = av.w;
        float4 bv = *(const float4*)(B + (size_t)(kt + bk) * NC + colBase + bn);
        *(float4*)&Bs[bk][bn] = bv;
        __syncthreads();
#pragma unroll
        for (int k = 0; k < 16; k++) {
            float4 a4 = *(float4*)&As[k][ty * 4];
            float4 b4 = *(float4*)&Bs[k][tx * 4];
            float ar_[4] = {a4.x, a4.y, a4.z, a4.w};
            float br_[4] = {b4.x, b4.y, b4.z, b4.w};
#pragma unroll
            for (int i = 0; i < 4; i++)
#pragma unroll
                for (int j = 0; j < 4; j++)
                    acc[i][j] = fmaf(ar_[i], br_[j], acc[i][j]);
        }
        __syncthreads();
    }
#pragma unroll
    for (int i = 0; i < 4; i++) {
        int r = rowBase + ty * 4 + i;
        if (r < M) {
            float4 o = make_float4(acc[i][0], acc[i][1], acc[i][2], acc[i][3]);
            *(float4*)(g_feat + (size_t)r * NC + colBase + tx * 4) = o;
        }
    }
}

// ---------------- el/er = <feat[n,h,:], al/ar[h,:]> ----------------
// one warp per (n,h)
__global__ void attn_scores(const float* __restrict__ al, const float* __restrict__ ar,
                            int Dpad, int Dlog)
{
    int gt = blockIdx.x * blockDim.x + threadIdx.x;
    int w = gt >> 5, lane = gt & 31;
    if (w >= NN * NH) return;
    int h = w & 3;
    const float* f = g_feat + (size_t)(w >> 2) * (NH * Dpad) + h * Dpad;
    float sl = 0.f, sr = 0.f;
    for (int j = lane; j < Dlog; j += 32) {
        float v = f[j];
        sl = fmaf(v, al[h * Dlog + j], sl);
        sr = fmaf(v, ar[h * Dlog + j], sr);
    }
#pragma unroll
    for (int o = 16; o; o >>= 1) {
        sl += __shfl_xor_sync(0xffffffffu, sl, o);
        sr += __shfl_xor_sync(0xffffffffu, sr, o);
    }
    if (!lane) { g_el[w] = sl; g_er[w] = sr; }
}

// ---------------- per-layer init: agg=0, m=-inf, den=0 ----------------
__global__ void init_layer(int total)
{
    int i = blockIdx.x * blockDim.x + threadIdx.x;
    if (i < total) g_agg[i] = 0.f;
    if (i < NN * NH) { g_m[i] = __int_as_float(0xff800000); g_den[i] = 0.f; }
}

// ---------------- pass 1: segment max over dst ----------------
__global__ void edge_max(const int* __restrict__ src, const int* __restrict__ dst)
{
    int e = blockIdx.x * blockDim.x + threadIdx.x;
    if (e >= NE) return;
    int s = src[e], d = dst[e];
    float4 a = *(const float4*)(g_el + s * 4);
    float4 b = *(const float4*)(g_er + d * 4);
    atomicMaxF(&g_m[d * 4 + 0], leaky(a.x + b.x));
    atomicMaxF(&g_m[d * 4 + 1], leaky(a.y + b.y));
    atomicMaxF(&g_m[d * 4 + 2], leaky(a.z + b.z));
    atomicMaxF(&g_m[d * 4 + 3], leaky(a.w + b.w));
}

// ---------------- pass 2: segment sum of exp ----------------
__global__ void edge_sum(const int* __restrict__ src, const int* __restrict__ dst)
{
    int e = blockIdx.x * blockDim.x + threadIdx.x;
    if (e >= NE) return;
    int s = src[e], d = dst[e];
    float4 a = *(const float4*)(g_el + s * 4);
    float4 b = *(const float4*)(g_er + d * 4);
    float4 mm = *(const float4*)(g_m + d * 4);
    float e0 = __expf(leaky(a.x + b.x) - mm.x);
    float e1 = __expf(leaky(a.y + b.y) - mm.y);
    float e2 = __expf(leaky(a.z + b.z) - mm.z);
    float e3 = __expf(leaky(a.w + b.w) - mm.w);
    asm volatile("red.global.add.v4.f32 [%0], {%1,%2,%3,%4};"
                 :: "l"(g_den + d * 4), "f"(e0), "f"(e1), "f"(e2), "f"(e3) : "memory");
}

// ---------------- pass 3: agg[dst] += alpha * feat[src] ----------------
// one warp per edge; alphas computed in lanes 0..3, shfl-broadcast
__global__ void edge_agg(const int* __restrict__ src, const int* __restrict__ dst,
                         int F, int dpad4)
{
    int gt = blockIdx.x * blockDim.x + threadIdx.x;
    int w = gt >> 5, lane = gt & 31;
    if (w >= NE) return;
    int s = src[w], d = dst[w];
    float alpha = 0.f;
    if (lane < NH) {
        float e = leaky(g_el[s * 4 + lane] + g_er[d * 4 + lane]);
        alpha = __expf(e - g_m[d * 4 + lane]) / g_den[d * 4 + lane];
    }
    const float* fs = g_feat + (size_t)s * F;
    float* od = g_agg + (size_t)d * F;
    int F4 = F >> 2;                      // 32 or 48 float4s per edge
    for (int q0 = 0; q0 < F4; q0 += 32) {
        int q = q0 + lane;
        int hd = (q < F4 ? q : F4 - 1) / dpad4;       // head index, all lanes participate
        float a = __shfl_sync(0xffffffffu, alpha, hd);
        if (q < F4) {
            float4 v = *(const float4*)(fs + q * 4);
            v.x *= a; v.y *= a; v.z *= a; v.w *= a;
            asm volatile("red.global.add.v4.f32 [%0], {%1,%2,%3,%4};"
                         :: "l"(od + q * 4), "f"(v.x), "f"(v.y), "f"(v.z), "f"(v.w)
                         : "memory");
        }
    }
}

// ---------------- bias + relu (layers 1-2, in place on g_agg) ----------------
__global__ void bias_relu(const float* __restrict__ b, int total)
{
    int i = blockIdx.x * blockDim.x + threadIdx.x;
    if (i >= total) return;
    float v = g_agg[i] + b[i & (F12 - 1)];
    g_agg[i] = v > 0.f ? v : 0.f;
}

// ---------------- pack W3 [128,188] -> [128,192] (pad each head 47->48) ----------------
__global__ void packW3(const float* __restrict__ W3)
{
    int i = blockIdx.x * blockDim.x + threadIdx.x;
    if (i >= F12 * F3) return;
    int r = i / F3, c = i % F3;
    int h = c / CPAD, cc = c % CPAD;
    g_W3p[i] = (cc < CC) ? W3[r * (NH * CC) + h * CC + cc] : 0.f;
}

// ---------------- finalize: bias, head mean, log_softmax -> out[N,47] ----------------
// one warp per node; lane covers class c and c+32
__global__ void finalize(const float* __restrict__ b3, float* __restrict__ out)
{
    int gt = blockIdx.x * blockDim.x + threadIdx.x;
    int n = gt >> 5, lane = gt & 31;
    if (n >= NN) return;
    const float* a = g_agg + (size_t)n * F3;
    const float NEG_INF = __int_as_float(0xff800000);
    float v0 = NEG_INF, v1 = NEG_INF;
    if (lane < CC) {
        float s = 0.f;
#pragma unroll
        for (int h = 0; h < NH; h++) s += a[h * CPAD + lane] + b3[h * CC + lane];
        v0 = 0.25f * s;
    }
    int c1 = lane + 32;
    if (c1 < CC) {
        float s = 0.f;
#pragma unroll
        for (int h = 0; h < NH; h++) s += a[h * CPAD + c1] + b3[h * CC + c1];
        v1 = 0.25f * s;
    }
    float mx = fmaxf(v0, v1);
#pragma unroll
    for (int o = 16; o; o >>= 1) mx = fmaxf(mx, __shfl_xor_sync(0xffffffffu, mx, o));
    float se = (lane < CC ? __expf(v0 - mx) : 0.f) + (c1 < CC ? __expf(v1 - mx) : 0.f);
#pragma unroll
    for (int o = 16; o; o >>= 1) se += __shfl_xor_sync(0xffffffffu, se, o);
    float lse = mx + __logf(se);
    if (lane < CC) out[n * CC + lane] = v0 - lse;
    if (c1 < CC)   out[n * CC + c1]   = v1 - lse;
}

// ---------------- launch ----------------
extern "C" void kernel_launch(void* const* d_in, const int* in_sizes, int n_in,
                              void* d_out, int out_size)
{
    const float* x   = (const float*)d_in[0];
    const int*   src = (const int*)d_in[1];
    const int*   dst = (const int*)d_in[2];
    const float* W1  = (const float*)d_in[3];
    const float* al1 = (const float*)d_in[4];
    const float* ar1 = (const float*)d_in[5];
    const float* b1  = (const float*)d_in[6];
    const float* W2  = (const float*)d_in[7];
    const float* al2 = (const float*)d_in[8];
    const float* ar2 = (const float*)d_in[9];
    const float* b2  = (const float*)d_in[10];
    const float* W3  = (const float*)d_in[11];
    const float* al3 = (const float*)d_in[12];
    const float* ar3 = (const float*)d_in[13];
    const float* b3  = (const float*)d_in[14];
    float* out = (float*)d_out;

    float *p_agg = nullptr, *p_w3p = nullptr;
    cudaGetSymbolAddress((void**)&p_agg, g_agg);
    cudaGetSymbolAddress((void**)&p_w3p, g_W3p);

    const int TB = 256;
    int gridRows = (NN + 63) / 64;
    int egrid  = (NE + TB - 1) / TB;
    int wegrid = (NE * 32 + TB - 1) / TB;        // warp per edge
    int nwgrid = (NN * NH * 32 + TB - 1) / TB;   // warp per (n,h)
    int f12grid = (NN * F12 + TB - 1) / TB;
    int f3grid  = (NN * F3 + TB - 1) / TB;

    // ---- layer 1: x[100k,256] -> 4 heads x 32 ----
    gemm64<<<dim3(F12 / 64, gridRows), TB>>>(x, W1, NN, IND, F12);
    attn_scores<<<nwgrid, TB>>>(al1, ar1, DD, DD);
    init_layer<<<f12grid, TB>>>(NN * F12);
    edge_max<<<egrid, TB>>>(src, dst);
    edge_sum<<<egrid, TB>>>(src, dst);
    edge_agg<<<wegrid, TB>>>(src, dst, F12, DD / 4);
    bias_relu<<<f12grid, TB>>>(b1, NN * F12);

    // ---- layer 2: 128 -> 128 ----
    gemm64<<<dim3(F12 / 64, gridRows), TB>>>(p_agg, W2, NN, F12, F12);
    attn_scores<<<nwgrid, TB>>>(al2, ar2, DD, DD);
    init_layer<<<f12grid, TB>>>(NN * F12);
    edge_max<<<egrid, TB>>>(src, dst);
    edge_sum<<<egrid, TB>>>(src, dst);
    edge_agg<<<wegrid, TB>>>(src, dst, F12, DD / 4);
    bias_relu<<<f12grid, TB>>>(b2, NN * F12);

    // ---- layer 3: 128 -> 4 heads x 47 (padded 48) ----
    packW3<<<(F12 * F3 + TB - 1) / TB, TB>>>(W3);
    gemm64<<<dim3(F3 / 64, gridRows), TB>>>(p_agg, p_w3p, NN, F12, F3);
    attn_scores<<<nwgrid, TB>>>(al3, ar3, CPAD, CC);
    init_layer<<<f3grid, TB>>>(NN * F3);
    edge_max<<<egrid, TB>>>(src, dst);
    edge_sum<<<egrid, TB>>>(src, dst);
    edge_agg<<<wegrid, TB>>>(src, dst, F3, CPAD / 4);
    finalize<<<(NN * 32 + TB - 1) / TB, TB>>>(b3, out);
}

// round 5
// speedup vs baseline: 1.6616x; 1.6616x over previous
#include <cuda_runtime.h>

// ---------------- problem constants ----------------
#define NN   100000      // nodes
#define NE   1600000     // edges
#define IND  256         // input dim
#define NH   4           // heads
#define DD   32          // hidden per head
#define CC   47          // classes
#define CPAD 48          // padded classes (float4-friendly)
#define F12  128         // H*D
#define F3   192         // H*CPAD
#define NEG  0.2f

#define SCAN_B 1024
#define SCAN_NB ((NN + SCAN_B - 1) / SCAN_B)   // 98

// ---------------- scratch (no allocs allowed) ----------------
__device__ float g_feat[(size_t)NN * F3];   // GEMM output (feat) per layer
__device__ float g_agg [(size_t)NN * F3];   // aggregation output / next-layer input
__device__ float g_el  [NN * NH];
__device__ float g_er  [NN * NH];
__device__ float g_W3p [F12 * F3];          // W3 padded 188 -> 192 cols
__device__ int   g_deg   [NN];
__device__ int   g_cursor[NN];
__device__ int   g_rowptr[NN + 1];
__device__ int   g_bsum  [SCAN_NB + 1];
__device__ int   g_csrsrc[NE];

__device__ __forceinline__ float leaky(float x) { return x > 0.f ? x : NEG * x; }

// ---------------- GEMM: g_feat = A[M,K] @ B[K,NC] ----------------
__global__ void gemm64(const float* __restrict__ A, const float* __restrict__ B,
                       int M, int K, int NC)
{
    __shared__ float As[16][68];
    __shared__ float Bs[16][68];
    int tid = threadIdx.x;
    int tx = tid & 15, ty = tid >> 4;
    int rowBase = blockIdx.y * 64;
    int colBase = blockIdx.x * 64;
    int lr = tid >> 2;
    int lk = (tid & 3) * 4;
    int bk = tid >> 4;
    int bn = (tid & 15) * 4;
    float acc[4][4] = {};

    for (int kt = 0; kt < K; kt += 16) {
        float4 av = make_float4(0.f, 0.f, 0.f, 0.f);
        int gr = rowBase + lr;
        if (gr < M) av = *(const float4*)(A + (size_t)gr * K + kt + lk);
        As[lk + 0][lr] = av.x; As[lk + 1][lr] = av.y;
        As[lk + 2][lr] = av.z; As[lk + 3][lr] = av.w;
        float4 bv = *(const float4*)(B + (size_t)(kt + bk) * NC + colBase + bn);
        *(float4*)&Bs[bk][bn] = bv;
        __syncthreads();
#pragma unroll
        for (int k = 0; k < 16; k++) {
            float4 a4 = *(float4*)&As[k][ty * 4];
            float4 b4 = *(float4*)&Bs[k][tx * 4];
            float ar_[4] = {a4.x, a4.y, a4.z, a4.w};
            float br_[4] = {b4.x, b4.y, b4.z, b4.w};
#pragma unroll
            for (int i = 0; i < 4; i++)
#pragma unroll
                for (int j = 0; j < 4; j++)
                    acc[i][j] = fmaf(ar_[i], br_[j], acc[i][j]);
        }
        __syncthreads();
    }
#pragma unroll
    for (int i = 0; i < 4; i++) {
        int r = rowBase + ty * 4 + i;
        if (r < M) {
            float4 o = make_float4(acc[i][0], acc[i][1], acc[i][2], acc[i][3]);
            *(float4*)(g_feat + (size_t)r * NC + colBase + tx * 4) = o;
        }
    }
}

// ---------------- el/er = <feat[n,h,:], al/ar[h,:]> ----------------
__global__ void attn_scores(const float* __restrict__ al, const float* __restrict__ ar,
                            int Dpad, int Dlog)
{
    int gt = blockIdx.x * blockDim.x + threadIdx.x;
    int w = gt >> 5, lane = gt & 31;
    if (w >= NN * NH) return;
    int h = w & 3;
    const float* f = g_feat + (size_t)(w >> 2) * (NH * Dpad) + h * Dpad;
    float sl = 0.f, sr = 0.f;
    for (int j = lane; j < Dlog; j += 32) {
        float v = f[j];
        sl = fmaf(v, al[h * Dlog + j], sl);
        sr = fmaf(v, ar[h * Dlog + j], sr);
    }
#pragma unroll
    for (int o = 16; o; o >>= 1) {
        sl += __shfl_xor_sync(0xffffffffu, sl, o);
        sr += __shfl_xor_sync(0xffffffffu, sr, o);
    }
    if (!lane) { g_el[w] = sl; g_er[w] = sr; }
}

// ---------------- CSR build (dst-sorted) ----------------
__global__ void zero_deg()
{
    int i = blockIdx.x * blockDim.x + threadIdx.x;
    if (i < NN) g_deg[i] = 0;
}

__global__ void csr_count(const int* __restrict__ dst)
{
    int e = blockIdx.x * blockDim.x + threadIdx.x;
    if (e < NE) atomicAdd(&g_deg[dst[e]], 1);
}

// block-local inclusive scan of deg -> g_rowptr[i+1]; block totals -> g_bsum
__global__ void scan1()
{
    __shared__ int sh[SCAN_B];
    int tid = threadIdx.x;
    int i = blockIdx.x * SCAN_B + tid;
    int v = (i < NN) ? g_deg[i] : 0;
    sh[tid] = v;
    __syncthreads();
#pragma unroll
    for (int off = 1; off < SCAN_B; off <<= 1) {
        int t = (tid >= off) ? sh[tid - off] : 0;
        __syncthreads();
        sh[tid] += t;
        __syncthreads();
    }
    if (i < NN) g_rowptr[i + 1] = sh[tid];
    if (tid == SCAN_B - 1) g_bsum[blockIdx.x] = sh[tid];
}

// exclusive scan of block sums (tiny, single thread)
__global__ void scan2()
{
    int run = 0;
    for (int b = 0; b < SCAN_NB; b++) {
        int v = g_bsum[b];
        g_bsum[b] = run;
        run += v;
    }
}

// add block offsets; produce rowptr (inclusive at i+1) and cursor (exclusive start)
__global__ void scan3()
{
    int i = blockIdx.x * SCAN_B + threadIdx.x;
    if (i >= NN) return;
    int off = g_bsum[blockIdx.x];
    int incl = g_rowptr[i + 1] + off;
    g_rowptr[i + 1] = incl;
    g_cursor[i] = incl - g_deg[i];
    if (i == 0) g_rowptr[0] = 0;
}

__global__ void csr_fill(const int* __restrict__ src, const int* __restrict__ dst)
{
    int e = blockIdx.x * blockDim.x + threadIdx.x;
    if (e >= NE) return;
    int pos = atomicAdd(&g_cursor[dst[e]], 1);
    g_csrsrc[pos] = src[e];
}

// ---------------- fused per-node gather: softmax + weighted aggregation ----------
// one warp per node. F in {128,192}; hq = chunks(float4) per head (8 or 12).
__device__ __forceinline__ float pick4(float x, float y, float z, float w, int h)
{
    return h < 2 ? (h == 0 ? x : y) : (h == 2 ? z : w);
}

__global__ void gat_gather(const float* __restrict__ bias, int F, int hq, int relu)
{
    int gt = blockIdx.x * blockDim.x + threadIdx.x;
    int n = gt >> 5, lane = gt & 31;
    if (n >= NN) return;
    int start = g_rowptr[n], end = g_rowptr[n + 1];
    float4 er4 = *(const float4*)(g_er + n * 4);
    const float NI = __int_as_float(0xff800000);

    // pass 1: per-head max over in-edges
    float4 mx = make_float4(NI, NI, NI, NI);
    for (int i = start + lane; i < end; i += 32) {
        int s = g_csrsrc[i];
        float4 el4 = *(const float4*)(g_el + s * 4);
        mx.x = fmaxf(mx.x, leaky(el4.x + er4.x));
        mx.y = fmaxf(mx.y, leaky(el4.y + er4.y));
        mx.z = fmaxf(mx.z, leaky(el4.z + er4.z));
        mx.w = fmaxf(mx.w, leaky(el4.w + er4.w));
    }
#pragma unroll
    for (int o = 16; o; o >>= 1) {
        mx.x = fmaxf(mx.x, __shfl_xor_sync(0xffffffffu, mx.x, o));
        mx.y = fmaxf(mx.y, __shfl_xor_sync(0xffffffffu, mx.y, o));
        mx.z = fmaxf(mx.z, __shfl_xor_sync(0xffffffffu, mx.z, o));
        mx.w = fmaxf(mx.w, __shfl_xor_sync(0xffffffffu, mx.w, o));
    }

    // pass 2: denominator
    float4 dn = make_float4(0.f, 0.f, 0.f, 0.f);
    for (int i = start + lane; i < end; i += 32) {
        int s = g_csrsrc[i];
        float4 el4 = *(const float4*)(g_el + s * 4);
        dn.x += __expf(leaky(el4.x + er4.x) - mx.x);
        dn.y += __expf(leaky(el4.y + er4.y) - mx.y);
        dn.z += __expf(leaky(el4.z + er4.z) - mx.z);
        dn.w += __expf(leaky(el4.w + er4.w) - mx.w);
    }
#pragma unroll
    for (int o = 16; o; o >>= 1) {
        dn.x += __shfl_xor_sync(0xffffffffu, dn.x, o);
        dn.y += __shfl_xor_sync(0xffffffffu, dn.y, o);
        dn.z += __shfl_xor_sync(0xffffffffu, dn.z, o);
        dn.w += __shfl_xor_sync(0xffffffffu, dn.w, o);
    }
    float4 ri;
    ri.x = __fdividef(1.f, dn.x); ri.y = __fdividef(1.f, dn.y);
    ri.z = __fdividef(1.f, dn.z); ri.w = __fdividef(1.f, dn.w);

    // pass 3: weighted aggregation, warp-parallel over feature chunks
    int F4 = F >> 2;
    int c0 = lane;
    int h0 = c0 / hq;
    int c1 = lane + 32;
    bool has2 = (c1 < F4);          // only for F=192, lanes 0..15
    int h1 = has2 ? (c1 / hq) : 0;
    float4 acc0 = make_float4(0.f, 0.f, 0.f, 0.f);
    float4 acc1 = make_float4(0.f, 0.f, 0.f, 0.f);

    int i = start;
    for (; i + 2 <= end; i += 2) {
        int s0 = g_csrsrc[i], s1 = g_csrsrc[i + 1];
        float4 ea = *(const float4*)(g_el + s0 * 4);
        float4 eb = *(const float4*)(g_el + s1 * 4);
        const float4* fa = (const float4*)(g_feat + (size_t)s0 * F);
        const float4* fbp = (const float4*)(g_feat + (size_t)s1 * F);
        float4 va = fa[c0];
        float4 vb = fbp[c0];
        float ax = __expf(leaky(ea.x + er4.x) - mx.x) * ri.x;
        float ay = __expf(leaky(ea.y + er4.y) - mx.y) * ri.y;
        float az = __expf(leaky(ea.z + er4.z) - mx.z) * ri.z;
        float aw = __expf(leaky(ea.w + er4.w) - mx.w) * ri.w;
        float bx = __expf(leaky(eb.x + er4.x) - mx.x) * ri.x;
        float by = __expf(leaky(eb.y + er4.y) - mx.y) * ri.y;
        float bz = __expf(leaky(eb.z + er4.z) - mx.z) * ri.z;
        float bw = __expf(leaky(eb.w + er4.w) - mx.w) * ri.w;
        float a0 = pick4(ax, ay, az, aw, h0);
        float b0 = pick4(bx, by, bz, bw, h0);
        acc0.x = fmaf(a0, va.x, fmaf(b0, vb.x, acc0.x));
        acc0.y = fmaf(a0, va.y, fmaf(b0, vb.y, acc0.y));
        acc0.z = fmaf(a0, va.z, fmaf(b0, vb.z, acc0.z));
        acc0.w = fmaf(a0, va.w, fmaf(b0, vb.w, acc0.w));
        if (has2) {
            float4 va1 = fa[c1];
            float4 vb1 = fbp[c1];
            float a1 = pick4(ax, ay, az, aw, h1);
            float b1 = pick4(bx, by, bz, bw, h1);
            acc1.x = fmaf(a1, va1.x, fmaf(b1, vb1.x, acc1.x));
            acc1.y = fmaf(a1, va1.y, fmaf(b1, vb1.y, acc1.y));
            acc1.z = fmaf(a1, va1.z, fmaf(b1, vb1.z, acc1.z));
            acc1.w = fmaf(a1, va1.w, fmaf(b1, vb1.w, acc1.w));
        }
    }
    if (i < end) {
        int s0 = g_csrsrc[i];
        float4 ea = *(const float4*)(g_el + s0 * 4);
        const float4* fa = (const float4*)(g_feat + (size_t)s0 * F);
        float4 va = fa[c0];
        float ax = __expf(leaky(ea.x + er4.x) - mx.x) * ri.x;
        float ay = __expf(leaky(ea.y + er4.y) - mx.y) * ri.y;
        float az = __expf(leaky(ea.z + er4.z) - mx.z) * ri.z;
        float aw = __expf(leaky(ea.w + er4.w) - mx.w) * ri.w;
        float a0 = pick4(ax, ay, az, aw, h0);
        acc0.x = fmaf(a0, va.x, acc0.x);
        acc0.y = fmaf(a0, va.y, acc0.y);
        acc0.z = fmaf(a0, va.z, acc0.z);
        acc0.w = fmaf(a0, va.w, acc0.w);
        if (has2) {
            float4 va1 = fa[c1];
            float a1 = pick4(ax, ay, az, aw, h1);
            acc1.x = fmaf(a1, va1.x, acc1.x);
            acc1.y = fmaf(a1, va1.y, acc1.y);
            acc1.z = fmaf(a1, va1.z, acc1.z);
            acc1.w = fmaf(a1, va1.w, acc1.w);
        }
    }

    float* od = g_agg + (size_t)n * F;
    if (bias) {
        float4 b4 = *(const float4*)(bias + c0 * 4);
        acc0.x += b4.x; acc0.y += b4.y; acc0.z += b4.z; acc0.w += b4.w;
    }
    if (relu) {
        acc0.x = fmaxf(acc0.x, 0.f); acc0.y = fmaxf(acc0.y, 0.f);
        acc0.z = fmaxf(acc0.z, 0.f); acc0.w = fmaxf(acc0.w, 0.f);
    }
    ((float4*)od)[c0] = acc0;
    if (has2) ((float4*)od)[c1] = acc1;
}

// ---------------- pack W3 [128,188] -> [128,192] ----------------
__global__ void packW3(const float* __restrict__ W3)
{
    int i = blockIdx.x * blockDim.x + threadIdx.x;
    if (i >= F12 * F3) return;
    int r = i / F3, c = i % F3;
    int h = c / CPAD, cc = c % CPAD;
    g_W3p[i] = (cc < CC) ? W3[r * (NH * CC) + h * CC + cc] : 0.f;
}

// ---------------- finalize: bias, head mean, log_softmax -> out[N,47] ----------------
__global__ void finalize(const float* __restrict__ b3, float* __restrict__ out)
{
    int gt = blockIdx.x * blockDim.x + threadIdx.x;
    int n = gt >> 5, lane = gt & 31;
    if (n >= NN) return;
    const float* a = g_agg + (size_t)n * F3;
    const float NEG_INF = __int_as_float(0xff800000);
    float v0 = NEG_INF, v1 = NEG_INF;
    if (lane < CC) {
        float s = 0.f;
#pragma unroll
        for (int h = 0; h < NH; h++) s += a[h * CPAD + lane] + b3[h * CC + lane];
        v0 = 0.25f * s;
    }
    int c1 = lane + 32;
    if (c1 < CC) {
        float s = 0.f;
#pragma unroll
        for (int h = 0; h < NH; h++) s += a[h * CPAD + c1] + b3[h * CC + c1];
        v1 = 0.25f * s;
    }
    float mxv = fmaxf(v0, v1);
#pragma unroll
    for (int o = 16; o; o >>= 1) mxv = fmaxf(mxv, __shfl_xor_sync(0xffffffffu, mxv, o));
    float se = (lane < CC ? __expf(v0 - mxv) : 0.f) + (c1 < CC ? __expf(v1 - mxv) : 0.f);
#pragma unroll
    for (int o = 16; o; o >>= 1) se += __shfl_xor_sync(0xffffffffu, se, o);
    float lse = mxv + __logf(se);
    if (lane < CC) out[n * CC + lane] = v0 - lse;
    if (c1 < CC)   out[n * CC + c1]   = v1 - lse;
}

// ---------------- launch ----------------
extern "C" void kernel_launch(void* const* d_in, const int* in_sizes, int n_in,
                              void* d_out, int out_size)
{
    const float* x   = (const float*)d_in[0];
    const int*   src = (const int*)d_in[1];
    const int*   dst = (const int*)d_in[2];
    const float* W1  = (const float*)d_in[3];
    const float* al1 = (const float*)d_in[4];
    const float* ar1 = (const float*)d_in[5];
    const float* b1  = (const float*)d_in[6];
    const float* W2  = (const float*)d_in[7];
    const float* al2 = (const float*)d_in[8];
    const float* ar2 = (const float*)d_in[9];
    const float* b2  = (const float*)d_in[10];
    const float* W3  = (const float*)d_in[11];
    const float* al3 = (const float*)d_in[12];
    const float* ar3 = (const float*)d_in[13];
    const float* b3  = (const float*)d_in[14];
    float* out = (float*)d_out;

    float *p_agg = nullptr, *p_w3p = nullptr;
    cudaGetSymbolAddress((void**)&p_agg, g_agg);
    cudaGetSymbolAddress((void**)&p_w3p, g_W3p);

    const int TB = 256;
    int gridRows = (NN + 63) / 64;
    int egrid  = (NE + TB - 1) / TB;
    int nwgrid = (NN * NH * 32 + TB - 1) / TB;   // warp per (n,h)
    int gwgrid = (NN * 32 + TB - 1) / TB;        // warp per node
    int ngrid  = (NN + TB - 1) / TB;

    // ---- build dst-CSR once (src/dst constant across layers) ----
    zero_deg<<<ngrid, TB>>>();
    csr_count<<<egrid, TB>>>(dst);
    scan1<<<SCAN_NB, SCAN_B>>>();
    scan2<<<1, 1>>>();
    scan3<<<SCAN_NB, SCAN_B>>>();
    csr_fill<<<egrid, TB>>>(src, dst);

    // ---- layer 1: x[100k,256] -> 4 heads x 32 ----
    gemm64<<<dim3(F12 / 64, gridRows), TB>>>(x, W1, NN, IND, F12);
    attn_scores<<<nwgrid, TB>>>(al1, ar1, DD, DD);
    gat_gather<<<gwgrid, TB>>>(b1, F12, DD / 4, 1);

    // ---- layer 2: 128 -> 128 ----
    gemm64<<<dim3(F12 / 64, gridRows), TB>>>(p_agg, W2, NN, F12, F12);
    attn_scores<<<nwgrid, TB>>>(al2, ar2, DD, DD);
    gat_gather<<<gwgrid, TB>>>(b2, F12, DD / 4, 1);

    // ---- layer 3: 128 -> 4 heads x 47 (padded 48) ----
    packW3<<<(F12 * F3 + TB - 1) / TB, TB>>>(W3);
    gemm64<<<dim3(F3 / 64, gridRows), TB>>>(p_agg, p_w3p, NN, F12, F3);
    attn_scores<<<nwgrid, TB>>>(al3, ar3, CPAD, CC);
    gat_gather<<<gwgrid, TB>>>(nullptr, F3, CPAD / 4, 0);
    finalize<<<(NN * 32 + TB - 1) / TB, TB>>>(b3, out);
}

// round 6
// speedup vs baseline: 1.7508x; 1.0537x over previous
#include <cuda_runtime.h>

// ---------------- problem constants ----------------
#define NN   100000      // nodes
#define NE   1600000     // edges
#define IND  256         // input dim
#define NH   4           // heads
#define DD   32          // hidden per head
#define CC   47          // classes
#define CPAD 48          // padded classes (float4-friendly)
#define F12  128         // H*D
#define F3   192         // H*CPAD
#define NEG  0.2f

#define SCAN_B 1024
#define SCAN_NB ((NN + SCAN_B - 1) / SCAN_B)   // 98

// GEMM tiling
#define BM 128
#define BN 64
#define BK 16

// ---------------- scratch (no allocs allowed) ----------------
__device__ float g_feat[(size_t)NN * F3];   // GEMM output (feat) per layer
__device__ float g_agg [(size_t)NN * F3];   // aggregation output / next-layer input
__device__ float g_el  [NN * NH];
__device__ float g_er  [NN * NH];
__device__ float g_W3p [F12 * F3];          // W3 padded 188 -> 192 cols
__device__ int   g_deg   [NN];
__device__ int   g_cursor[NN];
__device__ int   g_rowptr[NN + 1];
__device__ int   g_bsum  [SCAN_NB + 1];
__device__ int   g_csrsrc[NE];

__device__ __forceinline__ float leaky(float x) { return x > 0.f ? x : NEG * x; }

// ---------------- GEMM: g_feat = A[M,K] @ B[K,NC] ----------------
// BM=128 x BN=64 tile, 256 threads, 8x4 microtile, BK=16, double-buffered smem.
// Requires: K % 16 == 0, NC % 64 == 0 (true: K in {256,128}, NC in {128,192}).
__global__ __launch_bounds__(256) void gemm128(const float* __restrict__ A,
                                               const float* __restrict__ B,
                                               int M, int K, int NC)
{
    __shared__ float As[2][BK][BM + 4];   // As[b][k][m]
    __shared__ float Bs[2][BK][BN + 4];   // Bs[b][k][n]

    int tid = threadIdx.x;
    int tx = tid & 15;            // 0..15 -> N microtiles (4 each)
    int ty = tid >> 4;            // 0..15 -> M microtiles (8 each)
    int rowBase = blockIdx.y * BM;
    int colBase = blockIdx.x * BN;

    int ra = tid >> 2;            // 0..63  A row (and ra+64)
    int ka = (tid & 3) << 2;      // 0,4,8,12
    int rb = tid >> 4;            // 0..15  B k-row
    int cb = (tid & 15) << 2;     // 0..60  B col group

    const float* Aptr = A + (size_t)rowBase * K;
    const float* Bptr = B + colBase;

    const float4 z4 = make_float4(0.f, 0.f, 0.f, 0.f);
    float4 a0, a1, bv;

    // ---- prologue: tile 0 -> buf 0 ----
    {
        int gr0 = rowBase + ra, gr1 = gr0 + 64;
        a0 = (gr0 < M) ? *(const float4*)(Aptr + (size_t)ra * K + ka) : z4;
        a1 = (gr1 < M) ? *(const float4*)(Aptr + (size_t)(ra + 64) * K + ka) : z4;
        bv = *(const float4*)(Bptr + (size_t)rb * NC + cb);
        As[0][ka + 0][ra] = a0.x; As[0][ka + 1][ra] = a0.y;
        As[0][ka + 2][ra] = a0.z; As[0][ka + 3][ra] = a0.w;
        As[0][ka + 0][ra + 64] = a1.x; As[0][ka + 1][ra + 64] = a1.y;
        As[0][ka + 2][ra + 64] = a1.z; As[0][ka + 3][ra + 64] = a1.w;
        *(float4*)&Bs[0][rb][cb] = bv;
    }
    __syncthreads();

    float acc[8][4] = {};
    int nk = K / BK;
    int buf = 0;

    for (int kt = 0; kt < nk; kt++) {
        // prefetch next tile into registers
        if (kt + 1 < nk) {
            const float* Ak = Aptr + (kt + 1) * BK;
            int gr0 = rowBase + ra, gr1 = gr0 + 64;
            a0 = (gr0 < M) ? *(const float4*)(Ak + (size_t)ra * K + ka) : z4;
            a1 = (gr1 < M) ? *(const float4*)(Ak + (size_t)(ra + 64) * K + ka) : z4;
            bv = *(const float4*)(Bptr + (size_t)((kt + 1) * BK + rb) * NC + cb);
        }
        // compute on current buffer
#pragma unroll
        for (int k = 0; k < BK; k++) {
            float4 x0 = *(float4*)&As[buf][k][ty * 8];
            float4 x1 = *(float4*)&As[buf][k][ty * 8 + 4];
            float4 y  = *(float4*)&Bs[buf][k][tx * 4];
            float am[8] = {x0.x, x0.y, x0.z, x0.w, x1.x, x1.y, x1.z, x1.w};
            float bn[4] = {y.x, y.y, y.z, y.w};
#pragma unroll
            for (int i = 0; i < 8; i++)
#pragma unroll
                for (int j = 0; j < 4; j++)
                    acc[i][j] = fmaf(am[i], bn[j], acc[i][j]);
        }
        // commit prefetched tile to the other buffer
        if (kt + 1 < nk) {
            int nb = buf ^ 1;
            As[nb][ka + 0][ra] = a0.x; As[nb][ka + 1][ra] = a0.y;
            As[nb][ka + 2][ra] = a0.z; As[nb][ka + 3][ra] = a0.w;
            As[nb][ka + 0][ra + 64] = a1.x; As[nb][ka + 1][ra + 64] = a1.y;
            As[nb][ka + 2][ra + 64] = a1.z; As[nb][ka + 3][ra + 64] = a1.w;
            *(float4*)&Bs[nb][rb][cb] = bv;
            __syncthreads();
            buf = nb;
        }
    }

    // epilogue
#pragma unroll
    for (int i = 0; i < 8; i++) {
        int r = rowBase + ty * 8 + i;
        if (r < M) {
            float4 o = make_float4(acc[i][0], acc[i][1], acc[i][2], acc[i][3]);
            *(float4*)(g_feat + (size_t)r * NC + colBase + tx * 4) = o;
        }
    }
}

// ---------------- el/er = <feat[n,h,:], al/ar[h,:]> ----------------
__global__ void attn_scores(const float* __restrict__ al, const float* __restrict__ ar,
                            int Dpad, int Dlog)
{
    int gt = blockIdx.x * blockDim.x + threadIdx.x;
    int w = gt >> 5, lane = gt & 31;
    if (w >= NN * NH) return;
    int h = w & 3;
    const float* f = g_feat + (size_t)(w >> 2) * (NH * Dpad) + h * Dpad;
    float sl = 0.f, sr = 0.f;
    for (int j = lane; j < Dlog; j += 32) {
        float v = f[j];
        sl = fmaf(v, al[h * Dlog + j], sl);
        sr = fmaf(v, ar[h * Dlog + j], sr);
    }
#pragma unroll
    for (int o = 16; o; o >>= 1) {
        sl += __shfl_xor_sync(0xffffffffu, sl, o);
        sr += __shfl_xor_sync(0xffffffffu, sr, o);
    }
    if (!lane) { g_el[w] = sl; g_er[w] = sr; }
}

// ---------------- CSR build (dst-sorted) ----------------
__global__ void zero_deg()
{
    int i = blockIdx.x * blockDim.x + threadIdx.x;
    if (i < NN) g_deg[i] = 0;
}

__global__ void csr_count(const int* __restrict__ dst)
{
    int e = blockIdx.x * blockDim.x + threadIdx.x;
    if (e < NE) atomicAdd(&g_deg[dst[e]], 1);
}

// block-local inclusive scan of deg -> g_rowptr[i+1]; block totals -> g_bsum
__global__ void scan1()
{
    __shared__ int sh[SCAN_B];
    int tid = threadIdx.x;
    int i = blockIdx.x * SCAN_B + tid;
    int v = (i < NN) ? g_deg[i] : 0;
    sh[tid] = v;
    __syncthreads();
#pragma unroll
    for (int off = 1; off < SCAN_B; off <<= 1) {
        int t = (tid >= off) ? sh[tid - off] : 0;
        __syncthreads();
        sh[tid] += t;
        __syncthreads();
    }
    if (i < NN) g_rowptr[i + 1] = sh[tid];
    if (tid == SCAN_B - 1) g_bsum[blockIdx.x] = sh[tid];
}

// exclusive scan of block sums (one block, Hillis-Steele)
__global__ void scan2()
{
    __shared__ int sh[128];
    int tid = threadIdx.x;
    int v = (tid < SCAN_NB) ? g_bsum[tid] : 0;
    sh[tid] = v;
    __syncthreads();
#pragma unroll
    for (int off = 1; off < 128; off <<= 1) {
        int t = (tid >= off) ? sh[tid - off] : 0;
        __syncthreads();
        sh[tid] += t;
        __syncthreads();
    }
    if (tid < SCAN_NB) g_bsum[tid] = sh[tid] - v;   // exclusive
}

// add block offsets; produce rowptr (inclusive at i+1) and cursor (exclusive start)
__global__ void scan3()
{
    int i = blockIdx.x * SCAN_B + threadIdx.x;
    if (i >= NN) return;
    int off = g_bsum[blockIdx.x];
    int incl = g_rowptr[i + 1] + off;
    g_rowptr[i + 1] = incl;
    g_cursor[i] = incl - g_deg[i];
    if (i == 0) g_rowptr[0] = 0;
}

__global__ void csr_fill(const int* __restrict__ src, const int* __restrict__ dst)
{
    int e = blockIdx.x * blockDim.x + threadIdx.x;
    if (e >= NE) return;
    int pos = atomicAdd(&g_cursor[dst[e]], 1);
    g_csrsrc[pos] = src[e];
}

// ---------------- fused per-node gather: softmax + weighted aggregation ----------
// one warp per node. F in {128,192}; hq = chunks(float4) per head (8 or 12).
__device__ __forceinline__ float pick4(float x, float y, float z, float w, int h)
{
    return h < 2 ? (h == 0 ? x : y) : (h == 2 ? z : w);
}

__global__ void gat_gather(const float* __restrict__ bias, int F, int hq, int relu)
{
    int gt = blockIdx.x * blockDim.x + threadIdx.x;
    int n = gt >> 5, lane = gt & 31;
    if (n >= NN) return;
    int start = g_rowptr[n], end = g_rowptr[n + 1];
    float4 er4 = *(const float4*)(g_er + n * 4);
    const float NI = __int_as_float(0xff800000);

    // pass 1: per-head max over in-edges
    float4 mx = make_float4(NI, NI, NI, NI);
    for (int i = start + lane; i < end; i += 32) {
        int s = g_csrsrc[i];
        float4 el4 = *(const float4*)(g_el + s * 4);
        mx.x = fmaxf(mx.x, leaky(el4.x + er4.x));
        mx.y = fmaxf(mx.y, leaky(el4.y + er4.y));
        mx.z = fmaxf(mx.z, leaky(el4.z + er4.z));
        mx.w = fmaxf(mx.w, leaky(el4.w + er4.w));
    }
#pragma unroll
    for (int o = 16; o; o >>= 1) {
        mx.x = fmaxf(mx.x, __shfl_xor_sync(0xffffffffu, mx.x, o));
        mx.y = fmaxf(mx.y, __shfl_xor_sync(0xffffffffu, mx.y, o));
        mx.z = fmaxf(mx.z, __shfl_xor_sync(0xffffffffu, mx.z, o));
        mx.w = fmaxf(mx.w, __shfl_xor_sync(0xffffffffu, mx.w, o));
    }

    // pass 2: denominator
    float4 dn = make_float4(0.f, 0.f, 0.f, 0.f);
    for (int i = start + lane; i < end; i += 32) {
        int s = g_csrsrc[i];
        float4 el4 = *(const float4*)(g_el + s * 4);
        dn.x += __expf(leaky(el4.x + er4.x) - mx.x);
        dn.y += __expf(leaky(el4.y + er4.y) - mx.y);
        dn.z += __expf(leaky(el4.z + er4.z) - mx.z);
        dn.w += __expf(leaky(el4.w + er4.w) - mx.w);
    }
#pragma unroll
    for (int o = 16; o; o >>= 1) {
        dn.x += __shfl_xor_sync(0xffffffffu, dn.x, o);
        dn.y += __shfl_xor_sync(0xffffffffu, dn.y, o);
        dn.z += __shfl_xor_sync(0xffffffffu, dn.z, o);
        dn.w += __shfl_xor_sync(0xffffffffu, dn.w, o);
    }
    float4 ri;
    ri.x = __fdividef(1.f, dn.x); ri.y = __fdividef(1.f, dn.y);
    ri.z = __fdividef(1.f, dn.z); ri.w = __fdividef(1.f, dn.w);

    // pass 3: weighted aggregation, warp-parallel over feature chunks
    int F4 = F >> 2;
    int c0 = lane;
    int h0 = c0 / hq;
    int c1 = lane + 32;
    bool has2 = (c1 < F4);          // only for F=192, lanes 0..15
    int h1 = has2 ? (c1 / hq) : 0;
    float4 acc0 = make_float4(0.f, 0.f, 0.f, 0.f);
    float4 acc1 = make_float4(0.f, 0.f, 0.f, 0.f);

    int i = start;
    for (; i + 2 <= end; i += 2) {
        int s0 = g_csrsrc[i], s1 = g_csrsrc[i + 1];
        float4 ea = *(const float4*)(g_el + s0 * 4);
        float4 eb = *(const float4*)(g_el + s1 * 4);
        const float4* fa = (const float4*)(g_feat + (size_t)s0 * F);
        const float4* fbp = (const float4*)(g_feat + (size_t)s1 * F);
        float4 va = fa[c0];
        float4 vb = fbp[c0];
        float ax = __expf(leaky(ea.x + er4.x) - mx.x) * ri.x;
        float ay = __expf(leaky(ea.y + er4.y) - mx.y) * ri.y;
        float az = __expf(leaky(ea.z + er4.z) - mx.z) * ri.z;
        float aw = __expf(leaky(ea.w + er4.w) - mx.w) * ri.w;
        float bx = __expf(leaky(eb.x + er4.x) - mx.x) * ri.x;
        float by = __expf(leaky(eb.y + er4.y) - mx.y) * ri.y;
        float bz = __expf(leaky(eb.z + er4.z) - mx.z) * ri.z;
        float bw = __expf(leaky(eb.w + er4.w) - mx.w) * ri.w;
        float a0 = pick4(ax, ay, az, aw, h0);
        float b0 = pick4(bx, by, bz, bw, h0);
        acc0.x = fmaf(a0, va.x, fmaf(b0, vb.x, acc0.x));
        acc0.y = fmaf(a0, va.y, fmaf(b0, vb.y, acc0.y));
        acc0.z = fmaf(a0, va.z, fmaf(b0, vb.z, acc0.z));
        acc0.w = fmaf(a0, va.w, fmaf(b0, vb.w, acc0.w));
        if (has2) {
            float4 va1 = fa[c1];
            float4 vb1 = fbp[c1];
            float a1 = pick4(ax, ay, az, aw, h1);
            float b1 = pick4(bx, by, bz, bw, h1);
            acc1.x = fmaf(a1, va1.x, fmaf(b1, vb1.x, acc1.x));
            acc1.y = fmaf(a1, va1.y, fmaf(b1, vb1.y, acc1.y));
            acc1.z = fmaf(a1, va1.z, fmaf(b1, vb1.z, acc1.z));
            acc1.w = fmaf(a1, va1.w, fmaf(b1, vb1.w, acc1.w));
        }
    }
    if (i < end) {
        int s0 = g_csrsrc[i];
        float4 ea = *(const float4*)(g_el + s0 * 4);
        const float4* fa = (const float4*)(g_feat + (size_t)s0 * F);
        float4 va = fa[c0];
        float ax = __expf(leaky(ea.x + er4.x) - mx.x) * ri.x;
        float ay = __expf(leaky(ea.y + er4.y) - mx.y) * ri.y;
        float az = __expf(leaky(ea.z + er4.z) - mx.z) * ri.z;
        float aw = __expf(leaky(ea.w + er4.w) - mx.w) * ri.w;
        float a0 = pick4(ax, ay, az, aw, h0);
        acc0.x = fmaf(a0, va.x, acc0.x);
        acc0.y = fmaf(a0, va.y, acc0.y);
        acc0.z = fmaf(a0, va.z, acc0.z);
        acc0.w = fmaf(a0, va.w, acc0.w);
        if (has2) {
            float4 va1 = fa[c1];
            float a1 = pick4(ax, ay, az, aw, h1);
            acc1.x = fmaf(a1, va1.x, acc1.x);
            acc1.y = fmaf(a1, va1.y, acc1.y);
            acc1.z = fmaf(a1, va1.z, acc1.z);
            acc1.w = fmaf(a1, va1.w, acc1.w);
        }
    }

    float* od = g_agg + (size_t)n * F;
    if (bias) {
        float4 b4 = *(const float4*)(bias + c0 * 4);
        acc0.x += b4.x; acc0.y += b4.y; acc0.z += b4.z; acc0.w += b4.w;
    }
    if (relu) {
        acc0.x = fmaxf(acc0.x, 0.f); acc0.y = fmaxf(acc0.y, 0.f);
        acc0.z = fmaxf(acc0.z, 0.f); acc0.w = fmaxf(acc0.w, 0.f);
    }
    ((float4*)od)[c0] = acc0;
    if (has2) ((float4*)od)[c1] = acc1;
}

// ---------------- pack W3 [128,188] -> [128,192] ----------------
__global__ void packW3(const float* __restrict__ W3)
{
    int i = blockIdx.x * blockDim.x + threadIdx.x;
    if (i >= F12 * F3) return;
    int r = i / F3, c = i % F3;
    int h = c / CPAD, cc = c % CPAD;
    g_W3p[i] = (cc < CC) ? W3[r * (NH * CC) + h * CC + cc] : 0.f;
}

// ---------------- finalize: bias, head mean, log_softmax -> out[N,47] ----------------
__global__ void finalize(const float* __restrict__ b3, float* __restrict__ out)
{
    int gt = blockIdx.x * blockDim.x + threadIdx.x;
    int n = gt >> 5, lane = gt & 31;
    if (n >= NN) return;
    const float* a = g_agg + (size_t)n * F3;
    const float NEG_INF = __int_as_float(0xff800000);
    float v0 = NEG_INF, v1 = NEG_INF;
    if (lane < CC) {
        float s = 0.f;
#pragma unroll
        for (int h = 0; h < NH; h++) s += a[h * CPAD + lane] + b3[h * CC + lane];
        v0 = 0.25f * s;
    }
    int c1 = lane + 32;
    if (c1 < CC) {
        float s = 0.f;
#pragma unroll
        for (int h = 0; h < NH; h++) s += a[h * CPAD + c1] + b3[h * CC + c1];
        v1 = 0.25f * s;
    }
    float mxv = fmaxf(v0, v1);
#pragma unroll
    for (int o = 16; o; o >>= 1) mxv = fmaxf(mxv, __shfl_xor_sync(0xffffffffu, mxv, o));
    float se = (lane < CC ? __expf(v0 - mxv) : 0.f) + (c1 < CC ? __expf(v1 - mxv) : 0.f);
#pragma unroll
    for (int o = 16; o; o >>= 1) se += __shfl_xor_sync(0xffffffffu, se, o);
    float lse = mxv + __logf(se);
    if (lane < CC) out[n * CC + lane] = v0 - lse;
    if (c1 < CC)   out[n * CC + c1]   = v1 - lse;
}

// ---------------- launch ----------------
extern "C" void kernel_launch(void* const* d_in, const int* in_sizes, int n_in,
                              void* d_out, int out_size)
{
    const float* x   = (const float*)d_in[0];
    const int*   src = (const int*)d_in[1];
    const int*   dst = (const int*)d_in[2];
    const float* W1  = (const float*)d_in[3];
    const float* al1 = (const float*)d_in[4];
    const float* ar1 = (const float*)d_in[5];
    const float* b1  = (const float*)d_in[6];
    const float* W2  = (const float*)d_in[7];
    const float* al2 = (const float*)d_in[8];
    const float* ar2 = (const float*)d_in[9];
    const float* b2  = (const float*)d_in[10];
    const float* W3  = (const float*)d_in[11];
    const float* al3 = (const float*)d_in[12];
    const float* ar3 = (const float*)d_in[13];
    const float* b3  = (const float*)d_in[14];
    float* out = (float*)d_out;

    float *p_agg = nullptr, *p_w3p = nullptr;
    cudaGetSymbolAddress((void**)&p_agg, g_agg);
    cudaGetSymbolAddress((void**)&p_w3p, g_W3p);

    const int TB = 256;
    int gridRowsBM = (NN + BM - 1) / BM;         // 782
    int egrid  = (NE + TB - 1) / TB;
    int nwgrid = (NN * NH * 32 + TB - 1) / TB;   // warp per (n,h)
    int gwgrid = (NN * 32 + TB - 1) / TB;        // warp per node
    int ngrid  = (NN + TB - 1) / TB;

    // ---- build dst-CSR once (src/dst constant across layers) ----
    zero_deg<<<ngrid, TB>>>();
    csr_count<<<egrid, TB>>>(dst);
    scan1<<<SCAN_NB, SCAN_B>>>();
    scan2<<<1, 128>>>();
    scan3<<<SCAN_NB, SCAN_B>>>();
    csr_fill<<<egrid, TB>>>(src, dst);

    // ---- layer 1: x[100k,256] -> 4 heads x 32 ----
    gemm128<<<dim3(F12 / BN, gridRowsBM), TB>>>(x, W1, NN, IND, F12);
    attn_scores<<<nwgrid, TB>>>(al1, ar1, DD, DD);
    gat_gather<<<gwgrid, TB>>>(b1, F12, DD / 4, 1);

    // ---- layer 2: 128 -> 128 ----
    gemm128<<<dim3(F12 / BN, gridRowsBM), TB>>>(p_agg, W2, NN, F12, F12);
    attn_scores<<<nwgrid, TB>>>(al2, ar2, DD, DD);
    gat_gather<<<gwgrid, TB>>>(b2, F12, DD / 4, 1);

    // ---- layer 3: 128 -> 4 heads x 47 (padded 48) ----
    packW3<<<(F12 * F3 + TB - 1) / TB, TB>>>(W3);
    gemm128<<<dim3(F3 / BN, gridRowsBM), TB>>>(p_agg, p_w3p, NN, F12, F3);
    attn_scores<<<nwgrid, TB>>>(al3, ar3, CPAD, CC);
    gat_gather<<<gwgrid, TB>>>(nullptr, F3, CPAD / 4, 0);
    finalize<<<(NN * 32 + TB - 1) / TB, TB>>>(b3, out);
}

// round 7
// speedup vs baseline: 1.8244x; 1.0421x over previous
#include <cuda_runtime.h>
#include <cuda_fp16.h>

// ---------------- problem constants ----------------
#define NN   100000      // nodes
#define NE   1600000     // edges
#define IND  256         // input dim
#define NH   4           // heads
#define DD   32          // hidden per head
#define CC   47          // classes
#define CPAD 48          // padded classes (float4-friendly)
#define F12  128         // H*D
#define F3   192         // H*CPAD
#define NEG  0.2f

#define SCAN_B 1024
#define SCAN_NB ((NN + SCAN_B - 1) / SCAN_B)   // 98

// GEMM tiling
#define BM 128
#define BN 64
#define BK 16

// ---------------- scratch (no allocs allowed) ----------------
__device__ float  g_feat [(size_t)NN * F3];   // GEMM output (feat) per layer, fp32
__device__ __half g_feath[(size_t)NN * F3];   // fp16 copy for gather pass-3 reads
__device__ float  g_agg  [(size_t)NN * F3];   // aggregation output / next-layer input
__device__ float  g_el   [NN * NH];
__device__ float  g_er   [NN * NH];
__device__ float  g_W3p  [F12 * F3];          // W3 padded 188 -> 192 cols
__device__ int    g_deg   [NN];
__device__ int    g_cursor[NN];
__device__ int    g_rowptr[NN + 1];
__device__ int    g_bsum  [SCAN_NB + 1];
__device__ int    g_csrsrc[NE];

__device__ __forceinline__ float leaky(float x) { return x > 0.f ? x : NEG * x; }

// ---------------- GEMM: g_feat/g_feath = A[M,K] @ B[K,NC] ----------------
// BM=128 x BN=64 tile, 256 threads, 8x4 microtile, BK=16, double-buffered smem.
__global__ __launch_bounds__(256) void gemm128(const float* __restrict__ A,
                                               const float* __restrict__ B,
                                               int M, int K, int NC)
{
    __shared__ float As[2][BK][BM + 4];   // As[b][k][m]
    __shared__ float Bs[2][BK][BN + 4];   // Bs[b][k][n]

    int tid = threadIdx.x;
    int tx = tid & 15;            // 0..15 -> N microtiles (4 each)
    int ty = tid >> 4;            // 0..15 -> M microtiles (8 each)
    int rowBase = blockIdx.y * BM;
    int colBase = blockIdx.x * BN;

    int ra = tid >> 2;            // 0..63  A row (and ra+64)
    int ka = (tid & 3) << 2;      // 0,4,8,12
    int rb = tid >> 4;            // 0..15  B k-row
    int cb = (tid & 15) << 2;     // 0..60  B col group

    const float* Aptr = A + (size_t)rowBase * K;
    const float* Bptr = B + colBase;

    const float4 z4 = make_float4(0.f, 0.f, 0.f, 0.f);
    float4 a0, a1, bv;

    // ---- prologue: tile 0 -> buf 0 ----
    {
        int gr0 = rowBase + ra, gr1 = gr0 + 64;
        a0 = (gr0 < M) ? *(const float4*)(Aptr + (size_t)ra * K + ka) : z4;
        a1 = (gr1 < M) ? *(const float4*)(Aptr + (size_t)(ra + 64) * K + ka) : z4;
        bv = *(const float4*)(Bptr + (size_t)rb * NC + cb);
        As[0][ka + 0][ra] = a0.x; As[0][ka + 1][ra] = a0.y;
        As[0][ka + 2][ra] = a0.z; As[0][ka + 3][ra] = a0.w;
        As[0][ka + 0][ra + 64] = a1.x; As[0][ka + 1][ra + 64] = a1.y;
        As[0][ka + 2][ra + 64] = a1.z; As[0][ka + 3][ra + 64] = a1.w;
        *(float4*)&Bs[0][rb][cb] = bv;
    }
    __syncthreads();

    float acc[8][4] = {};
    int nk = K / BK;
    int buf = 0;

    for (int kt = 0; kt < nk; kt++) {
        if (kt + 1 < nk) {
            const float* Ak = Aptr + (kt + 1) * BK;
            int gr0 = rowBase + ra, gr1 = gr0 + 64;
            a0 = (gr0 < M) ? *(const float4*)(Ak + (size_t)ra * K + ka) : z4;
            a1 = (gr1 < M) ? *(const float4*)(Ak + (size_t)(ra + 64) * K + ka) : z4;
            bv = *(const float4*)(Bptr + (size_t)((kt + 1) * BK + rb) * NC + cb);
        }
#pragma unroll
        for (int k = 0; k < BK; k++) {
            float4 x0 = *(float4*)&As[buf][k][ty * 8];
            float4 x1 = *(float4*)&As[buf][k][ty * 8 + 4];
            float4 y  = *(float4*)&Bs[buf][k][tx * 4];
            float am[8] = {x0.x, x0.y, x0.z, x0.w, x1.x, x1.y, x1.z, x1.w};
            float bn[4] = {y.x, y.y, y.z, y.w};
#pragma unroll
            for (int i = 0; i < 8; i++)
#pragma unroll
                for (int j = 0; j < 4; j++)
                    acc[i][j] = fmaf(am[i], bn[j], acc[i][j]);
        }
        if (kt + 1 < nk) {
            int nb = buf ^ 1;
            As[nb][ka + 0][ra] = a0.x; As[nb][ka + 1][ra] = a0.y;
            As[nb][ka + 2][ra] = a0.z; As[nb][ka + 3][ra] = a0.w;
            As[nb][ka + 0][ra + 64] = a1.x; As[nb][ka + 1][ra + 64] = a1.y;
            As[nb][ka + 2][ra + 64] = a1.z; As[nb][ka + 3][ra + 64] = a1.w;
            *(float4*)&Bs[nb][rb][cb] = bv;
            __syncthreads();
            buf = nb;
        }
    }

    // epilogue: fp32 + fp16 stores
#pragma unroll
    for (int i = 0; i < 8; i++) {
        int r = rowBase + ty * 8 + i;
        if (r < M) {
            float4 o = make_float4(acc[i][0], acc[i][1], acc[i][2], acc[i][3]);
            *(float4*)(g_feat + (size_t)r * NC + colBase + tx * 4) = o;
            __half2 h0 = __floats2half2_rn(o.x, o.y);
            __half2 h1 = __floats2half2_rn(o.z, o.w);
            uint2 hu;
            hu.x = *(unsigned int*)&h0;
            hu.y = *(unsigned int*)&h1;
            *(uint2*)(g_feath + (size_t)r * NC + colBase + tx * 4) = hu;
        }
    }
}

// ---------------- el/er = <feat[n,h,:], al/ar[h,:]> ----------------
__global__ void attn_scores(const float* __restrict__ al, const float* __restrict__ ar,
                            int Dpad, int Dlog)
{
    int gt = blockIdx.x * blockDim.x + threadIdx.x;
    int w = gt >> 5, lane = gt & 31;
    if (w >= NN * NH) return;
    int h = w & 3;
    const float* f = g_feat + (size_t)(w >> 2) * (NH * Dpad) + h * Dpad;
    float sl = 0.f, sr = 0.f;
    for (int j = lane; j < Dlog; j += 32) {
        float v = f[j];
        sl = fmaf(v, al[h * Dlog + j], sl);
        sr = fmaf(v, ar[h * Dlog + j], sr);
    }
#pragma unroll
    for (int o = 16; o; o >>= 1) {
        sl += __shfl_xor_sync(0xffffffffu, sl, o);
        sr += __shfl_xor_sync(0xffffffffu, sr, o);
    }
    if (!lane) { g_el[w] = sl; g_er[w] = sr; }
}

// ---------------- CSR build (dst-sorted) ----------------
__global__ void zero_deg()
{
    int i = blockIdx.x * blockDim.x + threadIdx.x;
    if (i < NN) g_deg[i] = 0;
}

__global__ void csr_count(const int* __restrict__ dst)
{
    int e = blockIdx.x * blockDim.x + threadIdx.x;
    if (e < NE) atomicAdd(&g_deg[dst[e]], 1);
}

__global__ void scan1()
{
    __shared__ int sh[SCAN_B];
    int tid = threadIdx.x;
    int i = blockIdx.x * SCAN_B + tid;
    int v = (i < NN) ? g_deg[i] : 0;
    sh[tid] = v;
    __syncthreads();
#pragma unroll
    for (int off = 1; off < SCAN_B; off <<= 1) {
        int t = (tid >= off) ? sh[tid - off] : 0;
        __syncthreads();
        sh[tid] += t;
        __syncthreads();
    }
    if (i < NN) g_rowptr[i + 1] = sh[tid];
    if (tid == SCAN_B - 1) g_bsum[blockIdx.x] = sh[tid];
}

__global__ void scan2()
{
    __shared__ int sh[128];
    int tid = threadIdx.x;
    int v = (tid < SCAN_NB) ? g_bsum[tid] : 0;
    sh[tid] = v;
    __syncthreads();
#pragma unroll
    for (int off = 1; off < 128; off <<= 1) {
        int t = (tid >= off) ? sh[tid - off] : 0;
        __syncthreads();
        sh[tid] += t;
        __syncthreads();
    }
    if (tid < SCAN_NB) g_bsum[tid] = sh[tid] - v;   // exclusive
}

__global__ void scan3()
{
    int i = blockIdx.x * SCAN_B + threadIdx.x;
    if (i >= NN) return;
    int off = g_bsum[blockIdx.x];
    int incl = g_rowptr[i + 1] + off;
    g_rowptr[i + 1] = incl;
    g_cursor[i] = incl - g_deg[i];
    if (i == 0) g_rowptr[0] = 0;
}

__global__ void csr_fill(const int* __restrict__ src, const int* __restrict__ dst)
{
    int e = blockIdx.x * blockDim.x + threadIdx.x;
    if (e >= NE) return;
    int pos = atomicAdd(&g_cursor[dst[e]], 1);
    g_csrsrc[pos] = src[e];
}

// ---------------- fused per-node gather: softmax + weighted aggregation ----------
// one warp per node. F in {128,192}; hq = chunks(float4) per head (8 or 12).
// pass-3 feature reads come from the fp16 copy g_feath (half traffic).
__device__ __forceinline__ float pick4(float x, float y, float z, float w, int h)
{
    return h < 2 ? (h == 0 ? x : y) : (h == 2 ? z : w);
}

__device__ __forceinline__ void fma_h4(float4& acc, float a, uint2 hu)
{
    __half2 p0 = *(__half2*)&hu.x;
    __half2 p1 = *(__half2*)&hu.y;
    float2 f0 = __half22float2(p0);
    float2 f1 = __half22float2(p1);
    acc.x = fmaf(a, f0.x, acc.x);
    acc.y = fmaf(a, f0.y, acc.y);
    acc.z = fmaf(a, f1.x, acc.z);
    acc.w = fmaf(a, f1.y, acc.w);
}

__global__ void gat_gather(const float* __restrict__ bias, int F, int hq, int relu)
{
    int gt = blockIdx.x * blockDim.x + threadIdx.x;
    int n = gt >> 5, lane = gt & 31;
    if (n >= NN) return;
    int start = g_rowptr[n], end = g_rowptr[n + 1];
    float4 er4 = *(const float4*)(g_er + n * 4);
    const float NI = __int_as_float(0xff800000);

    // pass 1: per-head max over in-edges
    float4 mx = make_float4(NI, NI, NI, NI);
    for (int i = start + lane; i < end; i += 32) {
        int s = g_csrsrc[i];
        float4 el4 = *(const float4*)(g_el + s * 4);
        mx.x = fmaxf(mx.x, leaky(el4.x + er4.x));
        mx.y = fmaxf(mx.y, leaky(el4.y + er4.y));
        mx.z = fmaxf(mx.z, leaky(el4.z + er4.z));
        mx.w = fmaxf(mx.w, leaky(el4.w + er4.w));
    }
#pragma unroll
    for (int o = 16; o; o >>= 1) {
        mx.x = fmaxf(mx.x, __shfl_xor_sync(0xffffffffu, mx.x, o));
        mx.y = fmaxf(mx.y, __shfl_xor_sync(0xffffffffu, mx.y, o));
        mx.z = fmaxf(mx.z, __shfl_xor_sync(0xffffffffu, mx.z, o));
        mx.w = fmaxf(mx.w, __shfl_xor_sync(0xffffffffu, mx.w, o));
    }

    // pass 2: denominator
    float4 dn = make_float4(0.f, 0.f, 0.f, 0.f);
    for (int i = start + lane; i < end; i += 32) {
        int s = g_csrsrc[i];
        float4 el4 = *(const float4*)(g_el + s * 4);
        dn.x += __expf(leaky(el4.x + er4.x) - mx.x);
        dn.y += __expf(leaky(el4.y + er4.y) - mx.y);
        dn.z += __expf(leaky(el4.z + er4.z) - mx.z);
        dn.w += __expf(leaky(el4.w + er4.w) - mx.w);
    }
#pragma unroll
    for (int o = 16; o; o >>= 1) {
        dn.x += __shfl_xor_sync(0xffffffffu, dn.x, o);
        dn.y += __shfl_xor_sync(0xffffffffu, dn.y, o);
        dn.z += __shfl_xor_sync(0xffffffffu, dn.z, o);
        dn.w += __shfl_xor_sync(0xffffffffu, dn.w, o);
    }
    float4 ri;
    ri.x = __fdividef(1.f, dn.x); ri.y = __fdividef(1.f, dn.y);
    ri.z = __fdividef(1.f, dn.z); ri.w = __fdividef(1.f, dn.w);

    // pass 3: weighted aggregation over fp16 features
    int F4 = F >> 2;
    int c0 = lane;
    int h0 = c0 / hq;
    int c1 = lane + 32;
    bool has2 = (c1 < F4);          // only for F=192, lanes 0..15
    int h1 = has2 ? (c1 / hq) : 0;
    float4 acc0 = make_float4(0.f, 0.f, 0.f, 0.f);
    float4 acc1 = make_float4(0.f, 0.f, 0.f, 0.f);

    int i = start;
    for (; i + 2 <= end; i += 2) {
        int s0 = g_csrsrc[i], s1 = g_csrsrc[i + 1];
        float4 ea = *(const float4*)(g_el + s0 * 4);
        float4 eb = *(const float4*)(g_el + s1 * 4);
        const __half* fa = g_feath + (size_t)s0 * F;
        const __half* fb = g_feath + (size_t)s1 * F;
        uint2 ua0 = *(const uint2*)(fa + c0 * 4);
        uint2 ub0 = *(const uint2*)(fb + c0 * 4);
        float ax = __expf(leaky(ea.x + er4.x) - mx.x) * ri.x;
        float ay = __expf(leaky(ea.y + er4.y) - mx.y) * ri.y;
        float az = __expf(leaky(ea.z + er4.z) - mx.z) * ri.z;
        float aw = __expf(leaky(ea.w + er4.w) - mx.w) * ri.w;
        float bx = __expf(leaky(eb.x + er4.x) - mx.x) * ri.x;
        float by = __expf(leaky(eb.y + er4.y) - mx.y) * ri.y;
        float bz = __expf(leaky(eb.z + er4.z) - mx.z) * ri.z;
        float bw = __expf(leaky(eb.w + er4.w) - mx.w) * ri.w;
        float a0 = pick4(ax, ay, az, aw, h0);
        float b0 = pick4(bx, by, bz, bw, h0);
        fma_h4(acc0, a0, ua0);
        fma_h4(acc0, b0, ub0);
        if (has2) {
            uint2 ua1 = *(const uint2*)(fa + c1 * 4);
            uint2 ub1 = *(const uint2*)(fb + c1 * 4);
            float a1 = pick4(ax, ay, az, aw, h1);
            float b1 = pick4(bx, by, bz, bw, h1);
            fma_h4(acc1, a1, ua1);
            fma_h4(acc1, b1, ub1);
        }
    }
    if (i < end) {
        int s0 = g_csrsrc[i];
        float4 ea = *(const float4*)(g_el + s0 * 4);
        const __half* fa = g_feath + (size_t)s0 * F;
        uint2 ua0 = *(const uint2*)(fa + c0 * 4);
        float ax = __expf(leaky(ea.x + er4.x) - mx.x) * ri.x;
        float ay = __expf(leaky(ea.y + er4.y) - mx.y) * ri.y;
        float az = __expf(leaky(ea.z + er4.z) - mx.z) * ri.z;
        float aw = __expf(leaky(ea.w + er4.w) - mx.w) * ri.w;
        float a0 = pick4(ax, ay, az, aw, h0);
        fma_h4(acc0, a0, ua0);
        if (has2) {
            uint2 ua1 = *(const uint2*)(fa + c1 * 4);
            float a1 = pick4(ax, ay, az, aw, h1);
            fma_h4(acc1, a1, ua1);
        }
    }

    float* od = g_agg + (size_t)n * F;
    if (bias) {
        float4 b4 = *(const float4*)(bias + c0 * 4);
        acc0.x += b4.x; acc0.y += b4.y; acc0.z += b4.z; acc0.w += b4.w;
    }
    if (relu) {
        acc0.x = fmaxf(acc0.x, 0.f); acc0.y = fmaxf(acc0.y, 0.f);
        acc0.z = fmaxf(acc0.z, 0.f); acc0.w = fmaxf(acc0.w, 0.f);
    }
    ((float4*)od)[c0] = acc0;
    if (has2) ((float4*)od)[c1] = acc1;
}

// ---------------- pack W3 [128,188] -> [128,192] ----------------
__global__ void packW3(const float* __restrict__ W3)
{
    int i = blockIdx.x * blockDim.x + threadIdx.x;
    if (i >= F12 * F3) return;
    int r = i / F3, c = i % F3;
    int h = c / CPAD, cc = c % CPAD;
    g_W3p[i] = (cc < CC) ? W3[r * (NH * CC) + h * CC + cc] : 0.f;
}

// ---------------- finalize: bias, head mean, log_softmax -> out[N,47] ----------------
__global__ void finalize(const float* __restrict__ b3, float* __restrict__ out)
{
    int gt = blockIdx.x * blockDim.x + threadIdx.x;
    int n = gt >> 5, lane = gt & 31;
    if (n >= NN) return;
    const float* a = g_agg + (size_t)n * F3;
    const float NEG_INF = __int_as_float(0xff800000);
    float v0 = NEG_INF, v1 = NEG_INF;
    if (lane < CC) {
        float s = 0.f;
#pragma unroll
        for (int h = 0; h < NH; h++) s += a[h * CPAD + lane] + b3[h * CC + lane];
        v0 = 0.25f * s;
    }
    int c1 = lane + 32;
    if (c1 < CC) {
        float s = 0.f;
#pragma unroll
        for (int h = 0; h < NH; h++) s += a[h * CPAD + c1] + b3[h * CC + c1];
        v1 = 0.25f * s;
    }
    float mxv = fmaxf(v0, v1);
#pragma unroll
    for (int o = 16; o; o >>= 1) mxv = fmaxf(mxv, __shfl_xor_sync(0xffffffffu, mxv, o));
    float se = (lane < CC ? __expf(v0 - mxv) : 0.f) + (c1 < CC ? __expf(v1 - mxv) : 0.f);
#pragma unroll
    for (int o = 16; o; o >>= 1) se += __shfl_xor_sync(0xffffffffu, se, o);
    float lse = mxv + __logf(se);
    if (lane < CC) out[n * CC + lane] = v0 - lse;
    if (c1 < CC)   out[n * CC + c1]   = v1 - lse;
}

// ---------------- launch ----------------
extern "C" void kernel_launch(void* const* d_in, const int* in_sizes, int n_in,
                              void* d_out, int out_size)
{
    const float* x   = (const float*)d_in[0];
    const int*   src = (const int*)d_in[1];
    const int*   dst = (const int*)d_in[2];
    const float* W1  = (const float*)d_in[3];
    const float* al1 = (const float*)d_in[4];
    const float* ar1 = (const float*)d_in[5];
    const float* b1  = (const float*)d_in[6];
    const float* W2  = (const float*)d_in[7];
    const float* al2 = (const float*)d_in[8];
    const float* ar2 = (const float*)d_in[9];
    const float* b2  = (const float*)d_in[10];
    const float* W3  = (const float*)d_in[11];
    const float* al3 = (const float*)d_in[12];
    const float* ar3 = (const float*)d_in[13];
    const float* b3  = (const float*)d_in[14];
    float* out = (float*)d_out;

    float *p_agg = nullptr, *p_w3p = nullptr;
    cudaGetSymbolAddress((void**)&p_agg, g_agg);
    cudaGetSymbolAddress((void**)&p_w3p, g_W3p);

    const int TB = 256;
    int gridRowsBM = (NN + BM - 1) / BM;         // 782
    int egrid  = (NE + TB - 1) / TB;
    int nwgrid = (NN * NH * 32 + TB - 1) / TB;   // warp per (n,h)
    int gwgrid = (NN * 32 + TB - 1) / TB;        // warp per node
    int ngrid  = (NN + TB - 1) / TB;

    // ---- build dst-CSR once (src/dst constant across layers) ----
    zero_deg<<<ngrid, TB>>>();
    csr_count<<<egrid, TB>>>(dst);
    scan1<<<SCAN_NB, SCAN_B>>>();
    scan2<<<1, 128>>>();
    scan3<<<SCAN_NB, SCAN_B>>>();
    csr_fill<<<egrid, TB>>>(src, dst);

    // ---- layer 1: x[100k,256] -> 4 heads x 32 ----
    gemm128<<<dim3(F12 / BN, gridRowsBM), TB>>>(x, W1, NN, IND, F12);
    attn_scores<<<nwgrid, TB>>>(al1, ar1, DD, DD);
    gat_gather<<<gwgrid, TB>>>(b1, F12, DD / 4, 1);

    // ---- layer 2: 128 -> 128 ----
    gemm128<<<dim3(F12 / BN, gridRowsBM), TB>>>(p_agg, W2, NN, F12, F12);
    attn_scores<<<nwgrid, TB>>>(al2, ar2, DD, DD);
    gat_gather<<<gwgrid, TB>>>(b2, F12, DD / 4, 1);

    // ---- layer 3: 128 -> 4 heads x 47 (padded 48) ----
    packW3<<<(F12 * F3 + TB - 1) / TB, TB>>>(W3);
    gemm128<<<dim3(F3 / BN, gridRowsBM), TB>>>(p_agg, p_w3p, NN, F12, F3);
    attn_scores<<<nwgrid, TB>>>(al3, ar3, CPAD, CC);
    gat_gather<<<gwgrid, TB>>>(nullptr, F3, CPAD / 4, 0);
    finalize<<<(NN * 32 + TB - 1) / TB, TB>>>(b3, out);
}